// round 6
// baseline (speedup 1.0000x reference)
#include <cuda_runtime.h>
#include <math.h>

// Fixed problem shape (from reference_code)
#define MAXN 50000
#define MAXE 800000
#define FIN  128
#define FH   128
#define FOUT 40

// ---------------- device scratch (no allocations allowed) ----------------
__device__ __align__(16) float g_h[MAXN * FH];   // GEMM output (also 40-wide h)
__device__ __align__(16) float g_x[MAXN * FH];   // layer activations
__device__ float g_dinv[MAXN];
__device__ int   g_cnt[MAXN];
__device__ int   g_rowptr[MAXN + 1];
__device__ int   g_cursor[MAXN];
__device__ int   g_col[MAXE];
__device__ float g_w[MAXE];
// edge dtype detection state
__device__ int   g_mode;     // 0=int64, 1=int32, 2=float32, 3=float64
__device__ int   g_oddnz, g_evennz, g_bigint;

// ---------------- edge index access, dispatched on detected dtype -------
__device__ __forceinline__ int edge_at(const void* p, int idx, int mode) {
    switch (mode) {
        case 0:  return (int)((const long long*)p)[idx];
        case 1:  return ((const int*)p)[idx];
        case 2:  return (int)((const float*)p)[idx];
        default: return (int)((const double*)p)[idx];
    }
}

// ---------------- prep kernels ----------------
__global__ void init_flags_kernel(int n) {
    int i = blockIdx.x * blockDim.x + threadIdx.x;
    if (i == 0) { g_oddnz = 0; g_evennz = 0; g_bigint = 0; }
    if (i < n) g_cnt[i] = 0;
}

// Inspect first E (lo,hi) word pairs — safe under every candidate dtype.
__global__ void detect_kernel(const unsigned* __restrict__ w, int E, int n) {
    int i = blockIdx.x * blockDim.x + threadIdx.x;
    if (i < E) {
        unsigned lo = w[2 * i];
        unsigned hi = w[2 * i + 1];
        if (hi) atomicOr(&g_oddnz, 1);
        if (lo) atomicOr(&g_evennz, 1);
        if (lo >= (unsigned)n || hi >= (unsigned)n) atomicOr(&g_bigint, 1);
    }
}

__global__ void decide_kernel() {
    if (!g_oddnz)       g_mode = 0;   // int64
    else if (!g_evennz) g_mode = 3;   // float64
    else if (!g_bigint) g_mode = 1;   // int32
    else                g_mode = 2;   // float32
}

__global__ void count_kernel(const void* __restrict__ edges, int E, int n) {
    int i = blockIdx.x * blockDim.x + threadIdx.x;
    if (i < E) {
        int d = edge_at(edges, E + i, g_mode);
        if ((unsigned)d < (unsigned)n) atomicAdd(&g_cnt[d], 1);
    }
}

__global__ void dinv_kernel(int n) {
    int i = blockIdx.x * blockDim.x + threadIdx.x;
    if (i < n) {
        // +1 for the self-loop added by the reference
        g_dinv[i] = rsqrtf((float)(g_cnt[i] + 1));
    }
}

// single-block exclusive scan of g_cnt -> g_rowptr / g_cursor
__global__ void scan_kernel(int n) {
    __shared__ int sh[1024];
    int t = threadIdx.x;
    int carry = 0;
    for (int base = 0; base < n; base += 1024) {
        int v = (base + t < n) ? g_cnt[base + t] : 0;
        sh[t] = v;
        __syncthreads();
        for (int off = 1; off < 1024; off <<= 1) {
            int add = (t >= off) ? sh[t - off] : 0;
            __syncthreads();
            sh[t] += add;
            __syncthreads();
        }
        int incl = sh[t];
        if (base + t < n) {
            int excl = carry + incl - v;
            g_rowptr[base + t] = excl;
            g_cursor[base + t] = excl;
        }
        int tot = sh[1023];
        __syncthreads();
        carry += tot;
    }
    if (t == 0) g_rowptr[n] = carry;
}

__global__ void fill_kernel(const void* __restrict__ edges, int E, int n) {
    int i = blockIdx.x * blockDim.x + threadIdx.x;
    if (i < E) {
        int mode = g_mode;
        int s = edge_at(edges, i, mode);
        int d = edge_at(edges, E + i, mode);
        if ((unsigned)s < (unsigned)n && (unsigned)d < (unsigned)n) {
            int pos = atomicAdd(&g_cursor[d], 1);
            g_col[pos] = s;
            g_w[pos] = g_dinv[s] * g_dinv[d];
        }
    }
}

// ---------------- GEMM: g_h[n,128] = X[n,128] @ W[128,128] ----------------
// src_sel==0: X = Xext (harness input); src_sel==1: X = g_x (device global,
// resolved IN DEVICE CODE — never pass a __device__ symbol from host!).
// Block: 128 rows x 128 cols, 256 threads, microtile 8x(4+4), K chunks of 32.
#define XP 36
#define WP 132
__global__ __launch_bounds__(256) void gemm128_kernel(
    const float* __restrict__ Xext, const float* __restrict__ W,
    int src_sel, int n)
{
    __shared__ float sX[128 * XP];
    __shared__ float sW[32 * WP];

    const float* X = src_sel ? (const float*)g_x : Xext;

    int tid = threadIdx.x;
    int row0 = blockIdx.x * 128;

    int ty = tid >> 4;
    int tx = tid & 15;
    int r0 = ty * 8;
    int c0 = tx * 4;

    float acc[8][8];
#pragma unroll
    for (int i = 0; i < 8; i++)
#pragma unroll
        for (int j = 0; j < 8; j++) acc[i][j] = 0.0f;

    for (int k0 = 0; k0 < 128; k0 += 32) {
#pragma unroll
        for (int l = 0; l < 16; l++) {
            int idx = l * 256 + tid;
            int k = idx & 31;
            int r = idx >> 5;
            int row = row0 + r;
            sX[r * XP + k] = (row < n) ? X[row * 128 + k0 + k] : 0.0f;
        }
#pragma unroll
        for (int l = 0; l < 16; l++) {
            int idx = l * 256 + tid;
            int c = idx & 127;
            int k = idx >> 7;
            sW[k * WP + c] = W[(k0 + k) * 128 + c];
        }
        __syncthreads();

#pragma unroll
        for (int k = 0; k < 32; k++) {
            float xv[8];
#pragma unroll
            for (int i = 0; i < 8; i++) xv[i] = sX[(r0 + i) * XP + k];
            float4 wa = *(const float4*)&sW[k * WP + c0];
            float4 wb = *(const float4*)&sW[k * WP + 64 + c0];
#pragma unroll
            for (int i = 0; i < 8; i++) {
                acc[i][0] += xv[i] * wa.x; acc[i][1] += xv[i] * wa.y;
                acc[i][2] += xv[i] * wa.z; acc[i][3] += xv[i] * wa.w;
                acc[i][4] += xv[i] * wb.x; acc[i][5] += xv[i] * wb.y;
                acc[i][6] += xv[i] * wb.z; acc[i][7] += xv[i] * wb.w;
            }
        }
        __syncthreads();
    }

#pragma unroll
    for (int i = 0; i < 8; i++) {
        int row = row0 + r0 + i;
        if (row < n) {
            *(float4*)&g_h[row * 128 + c0] =
                make_float4(acc[i][0], acc[i][1], acc[i][2], acc[i][3]);
            *(float4*)&g_h[row * 128 + 64 + c0] =
                make_float4(acc[i][4], acc[i][5], acc[i][6], acc[i][7]);
        }
    }
}

// ---------------- GEMM: g_h[n,40] = g_x[n,128] @ W[128,40] ----------------
#define XPAD 132
__global__ __launch_bounds__(256) void gemm40_kernel(
    const float* __restrict__ W, int n)
{
    __shared__ float sW[128 * 40];
    __shared__ float sX[32 * XPAD];

    int tid = threadIdx.x;
    int row0 = blockIdx.x * 32;

    for (int idx = tid; idx < 128 * 40; idx += 256) sW[idx] = W[idx];
    for (int idx = tid; idx < 32 * 128; idx += 256) {
        int r = idx >> 7;
        int k = idx & 127;
        int row = row0 + r;
        sX[r * XPAD + k] = (row < n) ? g_x[row * 128 + k] : 0.0f;
    }
    __syncthreads();

    int ty = tid >> 3;
    int tx = tid & 7;
    int c0 = tx * 5;

    float acc[5] = {0, 0, 0, 0, 0};
#pragma unroll 4
    for (int k = 0; k < 128; k++) {
        float xv = sX[ty * XPAD + k];
#pragma unroll
        for (int j = 0; j < 5; j++) acc[j] += xv * sW[k * 40 + c0 + j];
    }

    int row = row0 + ty;
    if (row < n) {
#pragma unroll
        for (int j = 0; j < 5; j++) g_h[row * 40 + c0 + j] = acc[j];
    }
}

// ---------------- aggregation (128-dim): warp per node, float4 lanes ----
__global__ __launch_bounds__(128) void agg128_kernel(
    const float* __restrict__ b, int n)
{
    int warp = threadIdx.x >> 5;
    int lane = threadIdx.x & 31;
    int i = blockIdx.x * 4 + warp;
    if (i >= n) return;

    const float4* h4 = (const float4*)g_h;
    float4* x4 = (float4*)g_x;
    const float4* b4 = (const float4*)b;

    float di = g_dinv[i];
    float self_w = di * di;
    float4 hv = h4[i * 32 + lane];
    float4 acc;
    acc.x = hv.x * self_w; acc.y = hv.y * self_w;
    acc.z = hv.z * self_w; acc.w = hv.w * self_w;

    int s = g_rowptr[i];
    int e = g_rowptr[i + 1];
    for (int j = s; j < e; j++) {
        int c = g_col[j];
        float wt = g_w[j];
        float4 v = h4[c * 32 + lane];
        acc.x += wt * v.x; acc.y += wt * v.y;
        acc.z += wt * v.z; acc.w += wt * v.w;
    }
    float4 bv = b4[lane];
    acc.x = fmaxf(acc.x + bv.x, 0.0f);
    acc.y = fmaxf(acc.y + bv.y, 0.0f);
    acc.z = fmaxf(acc.z + bv.z, 0.0f);
    acc.w = fmaxf(acc.w + bv.w, 0.0f);
    x4[i * 32 + lane] = acc;
}

// ---------------- final: agg(40) + bias + relu + log_softmax -> out ----
__global__ __launch_bounds__(128) void agg40_lsm_kernel(
    const float* __restrict__ b, float* __restrict__ out, int n)
{
    int warp = threadIdx.x >> 5;
    int lane = threadIdx.x & 31;
    int i = blockIdx.x * 4 + warp;
    if (i >= n) return;

    float y0 = -INFINITY, y1 = -INFINITY;
    bool active = (lane < 20);
    int c0 = lane * 2;

    if (active) {
        float di = g_dinv[i];
        float self_w = di * di;
        const float2* h2 = (const float2*)g_h;
        float2 hv = h2[i * 20 + lane];
        float a0 = hv.x * self_w;
        float a1 = hv.y * self_w;
        int s = g_rowptr[i];
        int e = g_rowptr[i + 1];
        for (int j = s; j < e; j++) {
            int c = g_col[j];
            float wt = g_w[j];
            float2 v = h2[c * 20 + lane];
            a0 += wt * v.x;
            a1 += wt * v.y;
        }
        y0 = fmaxf(a0 + b[c0], 0.0f);
        y1 = fmaxf(a1 + b[c0 + 1], 0.0f);
    }

    float m = fmaxf(y0, y1);
#pragma unroll
    for (int off = 16; off > 0; off >>= 1)
        m = fmaxf(m, __shfl_xor_sync(0xFFFFFFFFu, m, off));

    float se = active ? (expf(y0 - m) + expf(y1 - m)) : 0.0f;
#pragma unroll
    for (int off = 16; off > 0; off >>= 1)
        se += __shfl_xor_sync(0xFFFFFFFFu, se, off);

    float lse = m + logf(se);
    if (active) {
        out[i * 40 + c0]     = y0 - lse;
        out[i * 40 + c0 + 1] = y1 - lse;
    }
}

// ---------------- launch (kernel launches ONLY — capture-safe; ----------
// ---------------- NO __device__ symbol is referenced from host) ---------
extern "C" void kernel_launch(void* const* d_in, const int* in_sizes, int n_in,
                              void* d_out, int out_size) {
    const float* x  = (const float*)d_in[0];
    const void*  ei = d_in[1];
    const float* W0 = (const float*)d_in[2];
    const float* b0 = (const float*)d_in[3];
    const float* W1 = (const float*)d_in[4];
    const float* b1 = (const float*)d_in[5];
    const float* W2 = (const float*)d_in[6];
    const float* b2 = (const float*)d_in[7];
    float* out = (float*)d_out;

    int n = in_sizes[0] / FIN;      // 50000
    int E = in_sizes[1] / 2;        // 800000

    const int TB = 256;
    int gN = (n + TB - 1) / TB;
    int gE = (E + TB - 1) / TB;
    int gWarp = (n + 3) / 4;
    int gGemm128 = (n + 127) / 128;
    int gGemm40  = (n + 31) / 32;

    // --- graph prep (recomputed every replay; deterministic work) ---
    init_flags_kernel<<<gN, TB>>>(n);
    detect_kernel<<<gE, TB>>>((const unsigned*)ei, E, n);
    decide_kernel<<<1, 1>>>();
    count_kernel<<<gE, TB>>>(ei, E, n);
    dinv_kernel<<<gN, TB>>>(n);
    scan_kernel<<<1, 1024>>>(n);
    fill_kernel<<<gE, TB>>>(ei, E, n);

    // --- layer 0 ---
    gemm128_kernel<<<gGemm128, 256>>>(x, W0, 0, n);
    agg128_kernel<<<gWarp, 128>>>(b0, n);
    // --- layer 1 (input = g_x, selected in device code) ---
    gemm128_kernel<<<gGemm128, 256>>>(x, W1, 1, n);
    agg128_kernel<<<gWarp, 128>>>(b1, n);
    // --- layer 2 + log_softmax ---
    gemm40_kernel<<<gGemm40, 256>>>(W2, n);
    agg40_lsm_kernel<<<gWarp, 128>>>(b2, out, n);
}